// round 6
// baseline (speedup 1.0000x reference)
#include <cuda_runtime.h>
#include <cstdint>

#define BATCH 8
#define CIN   64
#define COUT  64
#define Hdim  64
#define Wdim  64
#define CTOT  69
#define HW    (Hdim*Wdim)
#define NPIX  (BATCH*HW)

// Scratch (static device globals — no allocation)
__device__ float g_conv[BATCH*COUT*HW];   // raw conv output (pre-BN)
__device__ float g_sq[NPIX];              // 1x1-conv "shape query"
__device__ float g_mu[COUT];
__device__ float g_rs[COUT];

__device__ __forceinline__ int clampi(int v, int lo, int hi) {
    return v < lo ? lo : (v > hi ? hi : v);
}
__device__ __forceinline__ float f2tf32f(float f) {
    uint32_t r; asm("cvt.rna.tf32.f32 %0, %1;" : "=r"(r) : "f"(f));
    return __uint_as_float(r);
}

// m16n8k8 tf32 mma: D += A*B (D==C, fp32 accum). a: 4 regs, b: 2 regs.
__device__ __forceinline__ void mma8(float* d, const uint32_t* a, uint32_t b0, uint32_t b1) {
    asm volatile(
        "mma.sync.aligned.m16n8k8.row.col.f32.tf32.tf32.f32 "
        "{%0,%1,%2,%3}, {%4,%5,%6,%7}, {%8,%9}, {%0,%1,%2,%3};\n"
        : "+f"(d[0]), "+f"(d[1]), "+f"(d[2]), "+f"(d[3])
        : "r"(a[0]), "r"(a[1]), "r"(a[2]), "r"(a[3]), "r"(b0), "r"(b1));
}

// ---------------------------------------------------------------------------
// Kernel 1: 3x3 conv (replication pad) via mma.sync tf32 implicit GEMM.
// Block: 128 pixels (2 output rows) x 64 couts, 256 threads / 8 warps.
// Warp tile 32x32: 2 m16 tiles x 4 n8 tiles. K = 9 x (8 k8-steps over ci).
// A fragments read from a stride-264 x-slab (conflict-free banks).
// B fragments gathered in-kernel from cw (kidx-invariant offsets precomputed),
// register-prefetched one (ky,kx) chunk ahead.
// Grid: 256 blocks (b = blk>>5, h0 = (blk&31)*2).
// ---------------------------------------------------------------------------
#define SLAB_STRIDE 264
#define SLAB_FLOATS (64*SLAB_STRIDE)          // 16896
#define BBUF_FLOATS 4096
#define DYN_SMEM ((SLAB_FLOATS + BBUF_FLOATS) * 4)   // 83968 B

__global__ __launch_bounds__(256, 2) void conv_mma_kernel(
    const float* __restrict__ x, const float* __restrict__ cw,
    const float* __restrict__ cb)
{
    extern __shared__ float smem[];
    float* slab = smem;                 // [64 ci][256 rc] stride 264
    float* bbuf = smem + SLAB_FLOATS;   // B fragments for current (ky,kx)

    const int tid  = threadIdx.x;
    const int lane = tid & 31;
    const int w    = tid >> 5;
    const int gid  = lane >> 2;
    const int tig  = lane & 3;
    const int wm   = (w & 3) * 32;      // pixel offset
    const int wn   = (w >> 2) * 32;     // cout offset
    const int blk  = blockIdx.x;
    const int b    = blk >> 5;
    const int h0   = (blk & 31) * 2;

    // ---- precompute the 16 weight-gather offsets (kidx-invariant) ----
    // fragment flat index = 4*(j*256+tid)+e ; decode:
    //   r = flat&1, l2 = (flat>>1)&31, nt = (flat>>6)&7, kk = (flat>>9)&7
    //   co = nt*8 + (l2>>2), ci = kk*8 + (l2&3) + 4*r ; addr = (co*64+ci)*9 + kidx
    int wofs[4][4];
    #pragma unroll
    for (int j = 0; j < 4; j++) {
        int base = 4 * (j * 256 + tid);
        #pragma unroll
        for (int e = 0; e < 4; e++) {
            int flat = base + e;
            int r  = flat & 1;
            int l2 = (flat >> 1) & 31;
            int nt = (flat >> 6) & 7;
            int kk = (flat >> 9) & 7;
            int co = nt * 8 + (l2 >> 2);
            int ci = kk * 8 + (l2 & 3) + 4 * r;
            wofs[j][e] = (co * CIN + ci) * 9;
        }
    }

    // ---- slab fill: x[b][ci][h0-1..h0+2 clamped][:], tf32-rounded ----
    const float* xb = x + (size_t)b * CTOT * HW;
    #pragma unroll
    for (int i = 0; i < 64; i++) {
        int idx = i * 256 + tid;
        int ci  = idx >> 8;
        int rc  = idx & 255;
        int rr  = rc >> 6;
        int col = rc & 63;
        int row = clampi(h0 - 1 + rr, 0, Hdim - 1);
        slab[ci * SLAB_STRIDE + rc] = f2tf32f(__ldg(xb + (ci * Hdim + row) * Wdim + col));
    }

    // ---- prefetch B chunk kidx=0 (gather from cw) ----
    float4 pf[4];
    #pragma unroll
    for (int j = 0; j < 4; j++) {
        pf[j].x = f2tf32f(__ldg(cw + wofs[j][0]));
        pf[j].y = f2tf32f(__ldg(cw + wofs[j][1]));
        pf[j].z = f2tf32f(__ldg(cw + wofs[j][2]));
        pf[j].w = f2tf32f(__ldg(cw + wofs[j][3]));
    }

    float acc[2][4][4];
    #pragma unroll
    for (int tm = 0; tm < 2; tm++)
        #pragma unroll
        for (int nt = 0; nt < 4; nt++)
            #pragma unroll
            for (int c = 0; c < 4; c++) acc[tm][nt][c] = 0.f;

    __syncthreads();   // slab ready

    // per-tm fixed pixel geometry
    int dy[2], col_lo[2], col_hi[2];
    #pragma unroll
    for (int tm = 0; tm < 2; tm++) {
        int pix = wm + tm * 16 + gid;
        dy[tm] = pix >> 6;
        col_lo[tm] = pix & 63;
        col_hi[tm] = col_lo[tm] + 8;
    }

    float4* bb4 = (float4*)bbuf;

    for (int kidx = 0; kidx < 9; kidx++) {
        const int ky = kidx / 3, kx = kidx % 3;
        if (kidx > 0) __syncthreads();           // prior bbuf reads done
        #pragma unroll
        for (int j = 0; j < 4; j++) bb4[j * 256 + tid] = pf[j];
        __syncthreads();
        if (kidx < 8) {
            #pragma unroll
            for (int j = 0; j < 4; j++) {
                pf[j].x = f2tf32f(__ldg(cw + wofs[j][0] + kidx + 1));
                pf[j].y = f2tf32f(__ldg(cw + wofs[j][1] + kidx + 1));
                pf[j].z = f2tf32f(__ldg(cw + wofs[j][2] + kidx + 1));
                pf[j].w = f2tf32f(__ldg(cw + wofs[j][3] + kidx + 1));
            }
        }

        int off_lo[2], off_hi[2];
        #pragma unroll
        for (int tm = 0; tm < 2; tm++) {
            int rowoff = (dy[tm] + ky) * 64;
            off_lo[tm] = rowoff + clampi(col_lo[tm] + kx - 1, 0, 63);
            off_hi[tm] = rowoff + clampi(col_hi[tm] + kx - 1, 0, 63);
        }

        #pragma unroll
        for (int kk = 0; kk < 8; kk++) {
            const int cib  = (kk * 8 + tig) * SLAB_STRIDE;
            const int cib4 = cib + 4 * SLAB_STRIDE;
            uint32_t a[2][4];
            #pragma unroll
            for (int tm = 0; tm < 2; tm++) {
                a[tm][0] = __float_as_uint(slab[cib  + off_lo[tm]]);
                a[tm][1] = __float_as_uint(slab[cib  + off_hi[tm]]);
                a[tm][2] = __float_as_uint(slab[cib4 + off_lo[tm]]);
                a[tm][3] = __float_as_uint(slab[cib4 + off_hi[tm]]);
            }
            #pragma unroll
            for (int nt = 0; nt < 4; nt++) {
                int ntg = (wn >> 3) + nt;
                float2 bf = *(const float2*)&bbuf[((kk * 8 + ntg) * 32 + lane) * 2];
                uint32_t b0 = __float_as_uint(bf.x);
                uint32_t b1 = __float_as_uint(bf.y);
                mma8(acc[0][nt], a[0], b0, b1);
                mma8(acc[1][nt], a[1], b0, b1);
            }
        }
    }

    // ---- epilogue: +bias, write g_conv ----
    #pragma unroll
    for (int tm = 0; tm < 2; tm++) {
        float* grow = g_conv + ((size_t)b * COUT * Hdim + (h0 + dy[tm])) * Wdim;
        #pragma unroll
        for (int nt = 0; nt < 4; nt++) {
            int co0 = wn + nt * 8 + 2 * tig;
            float b0 = __ldg(cb + co0), b1 = __ldg(cb + co0 + 1);
            grow[(size_t)co0       * HW + col_lo[tm]] = acc[tm][nt][0] + b0;
            grow[(size_t)(co0 + 1) * HW + col_lo[tm]] = acc[tm][nt][1] + b1;
            grow[(size_t)co0       * HW + col_hi[tm]] = acc[tm][nt][2] + b0;
            grow[(size_t)(co0 + 1) * HW + col_hi[tm]] = acc[tm][nt][3] + b1;
        }
    }
}

// ---------------------------------------------------------------------------
// Kernel 2: BN stats, one block per channel, deterministic fixed-order tree
// ---------------------------------------------------------------------------
__global__ __launch_bounds__(256) void bn_stats()
{
    __shared__ float ss[256], ss2[256];
    const int co = blockIdx.x;
    const int t  = threadIdx.x;
    float s = 0.f, s2 = 0.f;
    #pragma unroll
    for (int b = 0; b < BATCH; b++) {
        const float4* p = (const float4*)(g_conv + ((size_t)(b * COUT + co)) * HW);
        #pragma unroll
        for (int j = 0; j < 4; j++) {
            float4 v = __ldg(p + t + j * 256);
            s  += v.x + v.y + v.z + v.w;
            s2 += v.x * v.x + v.y * v.y + v.z * v.z + v.w * v.w;
        }
    }
    ss[t] = s; ss2[t] = s2;
    __syncthreads();
    for (int o = 128; o > 0; o >>= 1) {
        if (t < o) { ss[t] += ss[t + o]; ss2[t] += ss2[t + o]; }
        __syncthreads();
    }
    if (t == 0) {
        float n   = (float)(BATCH * HW);
        float mu  = ss[0] / n;
        float var = ss2[0] / n - mu * mu;
        g_mu[co] = mu;
        g_rs[co] = rsqrtf(var + 1e-5f);
    }
}

// ---------------------------------------------------------------------------
// Kernel 3: codebook logits (dot-product form) + channel softmax +
//           BN-normalize + relu-attend + 1x1 conv to shape query.
// softmax(-|sw-k|^2) == softmax(2<sw,k> - |k|^2)  (|sw|^2 cancels)
// ---------------------------------------------------------------------------
__global__ __launch_bounds__(128) void attend_kernel(
    const float* __restrict__ x, const float* __restrict__ sk,
    const float* __restrict__ c2w, const float* __restrict__ c2b,
    float* __restrict__ out)
{
    __shared__ float s_k[64 * 45];
    __shared__ float s_k2[64];
    __shared__ float s_w2[64];
    __shared__ float s_mu[64];
    __shared__ float s_rs[64];
    __shared__ float s_e[128][65];

    const int tid = threadIdx.x;
    for (int i = tid; i < 64 * 45; i += 128) s_k[i] = sk[i];
    if (tid < 64) { s_w2[tid] = c2w[tid]; s_mu[tid] = g_mu[tid]; s_rs[tid] = g_rs[tid]; }
    __syncthreads();
    if (tid < 64) {
        float a = 0.f;
        #pragma unroll
        for (int t2 = 0; t2 < 45; t2++) {
            float kv = s_k[tid * 45 + t2];
            a = fmaf(kv, kv, a);
        }
        s_k2[tid] = a;
    }
    __syncthreads();

    const int p  = blockIdx.x * 128 + tid;
    const int b  = p >> 12;
    const int hw = p & 4095;
    const int h  = hw >> 6;
    const int w  = hw & 63;

    float sw[45];
    #pragma unroll
    for (int c = 0; c < 5; c++) {
        #pragma unroll
        for (int i = 0; i < 3; i++)
            #pragma unroll
            for (int j = 0; j < 3; j++) {
                int gy = clampi(h + i - 1, 0, Hdim - 1);
                int gx = clampi(w + j - 1, 0, Wdim - 1);
                sw[c * 9 + i * 3 + j] = x[((b * CTOT + 64 + c) * Hdim + gy) * Wdim + gx];
            }
    }
    #pragma unroll
    for (int c = 0; c < 2; c++) {
        float ctr = sw[c * 9 + 4];
        #pragma unroll
        for (int k = 0; k < 9; k++) sw[c * 9 + k] -= ctr;
    }

    // logits = 2<sw,k_co> - |k_co|^2
    float lmax = -3.4e38f;
    for (int co = 0; co < 64; co++) {
        float d = 0.f;
        #pragma unroll
        for (int t2 = 0; t2 < 45; t2++)
            d = fmaf(sw[t2], s_k[co * 45 + t2], d);
        float logit = 2.f * d - s_k2[co];
        s_e[tid][co] = logit;
        lmax = fmaxf(lmax, logit);
    }
    float se = 0.f;
    for (int co = 0; co < 64; co++) {
        float e = __expf(s_e[tid][co] - lmax);
        s_e[tid][co] = e;
        se += e;
    }
    float inv = 1.f / se;

    float sq = c2b[0];
    for (int co = 0; co < 64; co++) {
        float wv  = s_e[tid][co] * inv;
        float cv  = (g_conv[((b * COUT + co) * Hdim + h) * Wdim + w] - s_mu[co]) * s_rs[co];
        float att = fmaxf(cv * wv, 0.f);
        out[((b * CTOT + co) * Hdim + h) * Wdim + w] = att;
        sq = fmaf(s_w2[co], att, sq);
    }
    g_sq[p] = sq;
}

// ---------------------------------------------------------------------------
// Kernel 4: window softmax of shape query (zero-padded) + weighted stats
// ---------------------------------------------------------------------------
__global__ __launch_bounds__(256) void agg_kernel(
    const float* __restrict__ x, float* __restrict__ out)
{
    const int p = blockIdx.x * 256 + threadIdx.x;
    if (p >= NPIX) return;
    const int b  = p >> 12;
    const int hw = p & 4095;
    const int h  = hw >> 6;
    const int w  = hw & 63;

    float qv[9];
    float qmax = -3.4e38f;
    #pragma unroll
    for (int i = 0; i < 3; i++)
        #pragma unroll
        for (int j = 0; j < 3; j++) {
            int yy = h + i - 1, xx = w + j - 1;
            float v = 0.f;
            if (yy >= 0 && yy < Hdim && xx >= 0 && xx < Wdim)
                v = g_sq[(b << 12) + (yy << 6) + xx];
            qv[i * 3 + j] = v;
            qmax = fmaxf(qmax, v);
        }
    float qs = 0.f;
    #pragma unroll
    for (int k = 0; k < 9; k++) { qv[k] = __expf(qv[k] - qmax); qs += qv[k]; }
    float qinv = 1.f / qs;
    #pragma unroll
    for (int k = 0; k < 9; k++) qv[k] *= qinv;

    float win[5][9];
    #pragma unroll
    for (int c = 0; c < 5; c++) {
        #pragma unroll
        for (int i = 0; i < 3; i++)
            #pragma unroll
            for (int j = 0; j < 3; j++) {
                int gy = clampi(h + i - 1, 0, Hdim - 1);
                int gx = clampi(w + j - 1, 0, Wdim - 1);
                win[c][i * 3 + j] = x[((b * CTOT + 64 + c) * Hdim + gy) * Wdim + gx];
            }
    }

    float mean0 = 0.f, mean1 = 0.f, v1_0 = 0.f, v1_1 = 0.f, c1 = 0.f;
    #pragma unroll
    for (int k = 0; k < 9; k++) {
        mean0 = fmaf(win[0][k], qv[k], mean0);
        mean1 = fmaf(win[1][k], qv[k], mean1);
        v1_0  = fmaf(win[2][k], qv[k], v1_0);
        v1_1  = fmaf(win[3][k], qv[k], v1_1);
        c1    = fmaf(win[4][k], qv[k], c1);
    }
    float v2_0 = 0.f, v2_1 = 0.f, c2 = 0.f;
    #pragma unroll
    for (int k = 0; k < 9; k++) {
        float d0 = win[0][k] - mean0;
        float d1 = win[1][k] - mean1;
        v2_0 = fmaf(d0 * d0, qv[k], v2_0);
        v2_1 = fmaf(d1 * d1, qv[k], v2_1);
        c2   = fmaf(d0 * d1, qv[k], c2);
    }

    out[((b * CTOT + 64) * Hdim + h) * Wdim + w] = mean0;
    out[((b * CTOT + 65) * Hdim + h) * Wdim + w] = mean1;
    out[((b * CTOT + 66) * Hdim + h) * Wdim + w] = v1_0 + v2_0;
    out[((b * CTOT + 67) * Hdim + h) * Wdim + w] = v1_1 + v2_1;
    out[((b * CTOT + 68) * Hdim + h) * Wdim + w] = c1 + c2;
}

// ---------------------------------------------------------------------------
extern "C" void kernel_launch(void* const* d_in, const int* in_sizes, int n_in,
                              void* d_out, int out_size)
{
    const float* x   = (const float*)d_in[0];
    const float* cw  = (const float*)d_in[1];
    const float* cb  = (const float*)d_in[2];
    const float* c2w = (const float*)d_in[3];
    const float* c2b = (const float*)d_in[4];
    const float* sk  = (const float*)d_in[5];
    float* out = (float*)d_out;

    static bool attr_set = false;
    if (!attr_set) {
        cudaFuncSetAttribute(conv_mma_kernel,
                             cudaFuncAttributeMaxDynamicSharedMemorySize, DYN_SMEM);
        attr_set = true;
    }

    conv_mma_kernel<<<256, 256, DYN_SMEM>>>(x, cw, cb);
    bn_stats<<<64, 256>>>();
    attend_kernel<<<NPIX / 128, 128>>>(x, sk, c2w, c2b, out);
    agg_kernel<<<NPIX / 256, 256>>>(x, out);
}

// round 7
// speedup vs baseline: 1.4961x; 1.4961x over previous
#include <cuda_runtime.h>
#include <cstdint>

#define BATCH 8
#define CIN   64
#define COUT  64
#define Hdim  64
#define Wdim  64
#define CTOT  69
#define HW    (Hdim*Wdim)
#define NPIX  (BATCH*HW)

// Scratch (static device globals — no allocation)
__device__ float g_conv[BATCH*COUT*HW];   // raw conv output (pre-BN)
__device__ float g_sq[NPIX];              // 1x1-conv "shape query"
__device__ float g_mu[COUT];
__device__ float g_rs[COUT];
__device__ __align__(16) float g_wt[9*4096];  // weights in B-fragment order

__device__ __forceinline__ int clampi(int v, int lo, int hi) {
    return v < lo ? lo : (v > hi ? hi : v);
}
__device__ __forceinline__ float f2tf32f(float f) {
    uint32_t r; asm("cvt.rna.tf32.f32 %0, %1;" : "=r"(r) : "f"(f));
    return __uint_as_float(r);
}

// m16n8k8 tf32 mma: D += A*B (D==C, fp32 accum). a: 4 regs, b: 2 regs.
__device__ __forceinline__ void mma8(float* d, const uint32_t* a, uint32_t b0, uint32_t b1) {
    asm volatile(
        "mma.sync.aligned.m16n8k8.row.col.f32.tf32.tf32.f32 "
        "{%0,%1,%2,%3}, {%4,%5,%6,%7}, {%8,%9}, {%0,%1,%2,%3};\n"
        : "+f"(d[0]), "+f"(d[1]), "+f"(d[2]), "+f"(d[3])
        : "r"(a[0]), "r"(a[1]), "r"(a[2]), "r"(a[3]), "r"(b0), "r"(b1));
}

// ---------------------------------------------------------------------------
// Kernel 0: transform conv weights into B-fragment order (tf32-rounded).
// wt[(((kidx*8+kk)*8+nt)*32+lane)*2+r] = cw[co][ci][ky][kx]
//   co = nt*8 + (lane>>2), ci = kk*8 + (lane&3) + 4*r, kidx = ky*3+kx
// ---------------------------------------------------------------------------
__global__ __launch_bounds__(256) void wt_transform(const float* __restrict__ cw)
{
    int idx = blockIdx.x * 256 + threadIdx.x;
    if (idx >= 9 * 4096) return;
    int r    = idx & 1;
    int lane = (idx >> 1) & 31;
    int nt   = (idx >> 6) & 7;
    int kk   = (idx >> 9) & 7;
    int kidx = idx >> 12;
    int gid = lane >> 2, tig = lane & 3;
    int co = nt * 8 + gid;
    int ci = kk * 8 + tig + 4 * r;
    g_wt[idx] = f2tf32f(cw[(co * CIN + ci) * 9 + kidx]);
}

// ---------------------------------------------------------------------------
// Kernel 1: 3x3 conv (replication pad) via mma.sync tf32 implicit GEMM.
// Block: 128 pixels (2 output rows) x 64 couts, 256 threads / 8 warps.
// Warp tile 32x32: 2 m16 tiles x 4 n8 tiles. K = 9 x (8 k8-steps over ci).
// A fragments read directly from a stride-264 x-slab (conflict-free banks);
// B chunks streamed from fragment-ordered g_wt with register prefetch.
// Grid: 256 blocks (b = blk>>5, h0 = (blk&31)*2).
// ---------------------------------------------------------------------------
#define SLAB_STRIDE 264
#define SLAB_FLOATS (64*SLAB_STRIDE)          // 16896
#define BBUF_FLOATS 4096
#define DYN_SMEM ((SLAB_FLOATS + BBUF_FLOATS) * 4)   // 83968 B

__global__ __launch_bounds__(256, 2) void conv_mma_kernel(
    const float* __restrict__ x, const float* __restrict__ cb)
{
    extern __shared__ float smem[];
    float* slab = smem;                 // [64 ci][256 rc] stride 264
    float* bbuf = smem + SLAB_FLOATS;   // B fragments for current (ky,kx)

    const int tid  = threadIdx.x;
    const int lane = tid & 31;
    const int w    = tid >> 5;
    const int gid  = lane >> 2;
    const int tig  = lane & 3;
    const int wm   = (w & 3) * 32;      // pixel offset
    const int wn   = (w >> 2) * 32;     // cout offset
    const int blk  = blockIdx.x;
    const int b    = blk >> 5;
    const int h0   = (blk & 31) * 2;

    // ---- slab fill: x[b][ci][h0-1..h0+2 clamped][:], tf32-rounded ----
    const float* xb = x + (size_t)b * CTOT * HW;
    #pragma unroll
    for (int i = 0; i < 64; i++) {
        int idx = i * 256 + tid;
        int ci  = idx >> 8;
        int rc  = idx & 255;
        int rr  = rc >> 6;
        int col = rc & 63;
        int row = clampi(h0 - 1 + rr, 0, Hdim - 1);
        slab[ci * SLAB_STRIDE + rc] = f2tf32f(__ldg(xb + (ci * Hdim + row) * Wdim + col));
    }

    // ---- prefetch B chunk kidx=0 ----
    const float4* wt4 = (const float4*)g_wt;
    float4 pf[4];
    #pragma unroll
    for (int j = 0; j < 4; j++) pf[j] = __ldg(wt4 + j * 256 + tid);

    float acc[2][4][4];
    #pragma unroll
    for (int tm = 0; tm < 2; tm++)
        #pragma unroll
        for (int nt = 0; nt < 4; nt++)
            #pragma unroll
            for (int c = 0; c < 4; c++) acc[tm][nt][c] = 0.f;

    __syncthreads();   // slab ready

    // per-tm fixed pixel geometry
    int dy[2], col_lo[2], col_hi[2];
    #pragma unroll
    for (int tm = 0; tm < 2; tm++) {
        int pix = wm + tm * 16 + gid;
        dy[tm] = pix >> 6;
        col_lo[tm] = pix & 63;
        col_hi[tm] = col_lo[tm] + 8;
    }

    float4* bb4 = (float4*)bbuf;

    for (int kidx = 0; kidx < 9; kidx++) {
        const int ky = kidx / 3, kx = kidx % 3;
        if (kidx > 0) __syncthreads();           // prior bbuf reads done
        #pragma unroll
        for (int j = 0; j < 4; j++) bb4[j * 256 + tid] = pf[j];
        __syncthreads();
        if (kidx < 8) {
            #pragma unroll
            for (int j = 0; j < 4; j++)
                pf[j] = __ldg(wt4 + (kidx + 1) * 1024 + j * 256 + tid);
        }

        int off_lo[2], off_hi[2];
        #pragma unroll
        for (int tm = 0; tm < 2; tm++) {
            int rowoff = (dy[tm] + ky) * 64;
            off_lo[tm] = rowoff + clampi(col_lo[tm] + kx - 1, 0, 63);
            off_hi[tm] = rowoff + clampi(col_hi[tm] + kx - 1, 0, 63);
        }

        #pragma unroll
        for (int kk = 0; kk < 8; kk++) {
            const int cib  = (kk * 8 + tig) * SLAB_STRIDE;
            const int cib4 = cib + 4 * SLAB_STRIDE;
            uint32_t a[2][4];
            #pragma unroll
            for (int tm = 0; tm < 2; tm++) {
                a[tm][0] = __float_as_uint(slab[cib  + off_lo[tm]]);
                a[tm][1] = __float_as_uint(slab[cib  + off_hi[tm]]);
                a[tm][2] = __float_as_uint(slab[cib4 + off_lo[tm]]);
                a[tm][3] = __float_as_uint(slab[cib4 + off_hi[tm]]);
            }
            #pragma unroll
            for (int nt = 0; nt < 4; nt++) {
                int ntg = (wn >> 3) + nt;
                float2 bf = *(const float2*)&bbuf[((kk * 8 + ntg) * 32 + lane) * 2];
                uint32_t b0 = __float_as_uint(bf.x);
                uint32_t b1 = __float_as_uint(bf.y);
                mma8(acc[0][nt], a[0], b0, b1);
                mma8(acc[1][nt], a[1], b0, b1);
            }
        }
    }

    // ---- epilogue: +bias, write g_conv ----
    #pragma unroll
    for (int tm = 0; tm < 2; tm++) {
        float* grow = g_conv + ((size_t)b * COUT * Hdim + (h0 + dy[tm])) * Wdim;
        #pragma unroll
        for (int nt = 0; nt < 4; nt++) {
            int co0 = wn + nt * 8 + 2 * tig;
            float b0 = __ldg(cb + co0), b1 = __ldg(cb + co0 + 1);
            grow[(size_t)co0       * HW + col_lo[tm]] = acc[tm][nt][0] + b0;
            grow[(size_t)(co0 + 1) * HW + col_lo[tm]] = acc[tm][nt][1] + b1;
            grow[(size_t)co0       * HW + col_hi[tm]] = acc[tm][nt][2] + b0;
            grow[(size_t)(co0 + 1) * HW + col_hi[tm]] = acc[tm][nt][3] + b1;
        }
    }
}

// ---------------------------------------------------------------------------
// Kernel 2: BN stats, one block per channel, deterministic fixed-order tree
// ---------------------------------------------------------------------------
__global__ __launch_bounds__(256) void bn_stats()
{
    __shared__ float ss[256], ss2[256];
    const int co = blockIdx.x;
    const int t  = threadIdx.x;
    float s = 0.f, s2 = 0.f;
    #pragma unroll
    for (int b = 0; b < BATCH; b++) {
        const float4* p = (const float4*)(g_conv + ((size_t)(b * COUT + co)) * HW);
        #pragma unroll
        for (int j = 0; j < 4; j++) {
            float4 v = __ldg(p + t + j * 256);
            s  += v.x + v.y + v.z + v.w;
            s2 += v.x * v.x + v.y * v.y + v.z * v.z + v.w * v.w;
        }
    }
    ss[t] = s; ss2[t] = s2;
    __syncthreads();
    for (int o = 128; o > 0; o >>= 1) {
        if (t < o) { ss[t] += ss[t + o]; ss2[t] += ss2[t + o]; }
        __syncthreads();
    }
    if (t == 0) {
        float n   = (float)(BATCH * HW);
        float mu  = ss[0] / n;
        float var = ss2[0] / n - mu * mu;
        g_mu[co] = mu;
        g_rs[co] = rsqrtf(var + 1e-5f);
    }
}

// ---------------------------------------------------------------------------
// Kernel 3: codebook logits (dot-product form) + channel softmax +
//           BN-normalize + relu-attend + 1x1 conv to shape query.
// softmax(-|sw-k|^2) == softmax(2<sw,k> - |k|^2)  (|sw|^2 cancels)
// ---------------------------------------------------------------------------
__global__ __launch_bounds__(128) void attend_kernel(
    const float* __restrict__ x, const float* __restrict__ sk,
    const float* __restrict__ c2w, const float* __restrict__ c2b,
    float* __restrict__ out)
{
    __shared__ float s_k[64 * 45];
    __shared__ float s_k2[64];
    __shared__ float s_w2[64];
    __shared__ float s_mu[64];
    __shared__ float s_rs[64];
    __shared__ float s_e[128][65];

    const int tid = threadIdx.x;
    for (int i = tid; i < 64 * 45; i += 128) s_k[i] = sk[i];
    if (tid < 64) { s_w2[tid] = c2w[tid]; s_mu[tid] = g_mu[tid]; s_rs[tid] = g_rs[tid]; }
    __syncthreads();
    if (tid < 64) {
        float a = 0.f;
        #pragma unroll
        for (int t2 = 0; t2 < 45; t2++) {
            float kv = s_k[tid * 45 + t2];
            a = fmaf(kv, kv, a);
        }
        s_k2[tid] = a;
    }
    __syncthreads();

    const int p  = blockIdx.x * 128 + tid;
    const int b  = p >> 12;
    const int hw = p & 4095;
    const int h  = hw >> 6;
    const int w  = hw & 63;

    float sw[45];
    #pragma unroll
    for (int c = 0; c < 5; c++) {
        #pragma unroll
        for (int i = 0; i < 3; i++)
            #pragma unroll
            for (int j = 0; j < 3; j++) {
                int gy = clampi(h + i - 1, 0, Hdim - 1);
                int gx = clampi(w + j - 1, 0, Wdim - 1);
                sw[c * 9 + i * 3 + j] = x[((b * CTOT + 64 + c) * Hdim + gy) * Wdim + gx];
            }
    }
    #pragma unroll
    for (int c = 0; c < 2; c++) {
        float ctr = sw[c * 9 + 4];
        #pragma unroll
        for (int k = 0; k < 9; k++) sw[c * 9 + k] -= ctr;
    }

    // logits = 2<sw,k_co> - |k_co|^2
    float lmax = -3.4e38f;
    for (int co = 0; co < 64; co++) {
        float d = 0.f;
        #pragma unroll
        for (int t2 = 0; t2 < 45; t2++)
            d = fmaf(sw[t2], s_k[co * 45 + t2], d);
        float logit = 2.f * d - s_k2[co];
        s_e[tid][co] = logit;
        lmax = fmaxf(lmax, logit);
    }
    float se = 0.f;
    for (int co = 0; co < 64; co++) {
        float e = __expf(s_e[tid][co] - lmax);
        s_e[tid][co] = e;
        se += e;
    }
    float inv = 1.f / se;

    float sq = c2b[0];
    for (int co = 0; co < 64; co++) {
        float wv  = s_e[tid][co] * inv;
        float cv  = (g_conv[((b * COUT + co) * Hdim + h) * Wdim + w] - s_mu[co]) * s_rs[co];
        float att = fmaxf(cv * wv, 0.f);
        out[((b * CTOT + co) * Hdim + h) * Wdim + w] = att;
        sq = fmaf(s_w2[co], att, sq);
    }
    g_sq[p] = sq;
}

// ---------------------------------------------------------------------------
// Kernel 4: window softmax of shape query (zero-padded) + weighted stats
// ---------------------------------------------------------------------------
__global__ __launch_bounds__(256) void agg_kernel(
    const float* __restrict__ x, float* __restrict__ out)
{
    const int p = blockIdx.x * 256 + threadIdx.x;
    if (p >= NPIX) return;
    const int b  = p >> 12;
    const int hw = p & 4095;
    const int h  = hw >> 6;
    const int w  = hw & 63;

    float qv[9];
    float qmax = -3.4e38f;
    #pragma unroll
    for (int i = 0; i < 3; i++)
        #pragma unroll
        for (int j = 0; j < 3; j++) {
            int yy = h + i - 1, xx = w + j - 1;
            float v = 0.f;
            if (yy >= 0 && yy < Hdim && xx >= 0 && xx < Wdim)
                v = g_sq[(b << 12) + (yy << 6) + xx];
            qv[i * 3 + j] = v;
            qmax = fmaxf(qmax, v);
        }
    float qs = 0.f;
    #pragma unroll
    for (int k = 0; k < 9; k++) { qv[k] = __expf(qv[k] - qmax); qs += qv[k]; }
    float qinv = 1.f / qs;
    #pragma unroll
    for (int k = 0; k < 9; k++) qv[k] *= qinv;

    float win[5][9];
    #pragma unroll
    for (int c = 0; c < 5; c++) {
        #pragma unroll
        for (int i = 0; i < 3; i++)
            #pragma unroll
            for (int j = 0; j < 3; j++) {
                int gy = clampi(h + i - 1, 0, Hdim - 1);
                int gx = clampi(w + j - 1, 0, Wdim - 1);
                win[c][i * 3 + j] = x[((b * CTOT + 64 + c) * Hdim + gy) * Wdim + gx];
            }
    }

    float mean0 = 0.f, mean1 = 0.f, v1_0 = 0.f, v1_1 = 0.f, c1 = 0.f;
    #pragma unroll
    for (int k = 0; k < 9; k++) {
        mean0 = fmaf(win[0][k], qv[k], mean0);
        mean1 = fmaf(win[1][k], qv[k], mean1);
        v1_0  = fmaf(win[2][k], qv[k], v1_0);
        v1_1  = fmaf(win[3][k], qv[k], v1_1);
        c1    = fmaf(win[4][k], qv[k], c1);
    }
    float v2_0 = 0.f, v2_1 = 0.f, c2 = 0.f;
    #pragma unroll
    for (int k = 0; k < 9; k++) {
        float d0 = win[0][k] - mean0;
        float d1 = win[1][k] - mean1;
        v2_0 = fmaf(d0 * d0, qv[k], v2_0);
        v2_1 = fmaf(d1 * d1, qv[k], v2_1);
        c2   = fmaf(d0 * d1, qv[k], c2);
    }

    out[((b * CTOT + 64) * Hdim + h) * Wdim + w] = mean0;
    out[((b * CTOT + 65) * Hdim + h) * Wdim + w] = mean1;
    out[((b * CTOT + 66) * Hdim + h) * Wdim + w] = v1_0 + v2_0;
    out[((b * CTOT + 67) * Hdim + h) * Wdim + w] = v1_1 + v2_1;
    out[((b * CTOT + 68) * Hdim + h) * Wdim + w] = c1 + c2;
}

// ---------------------------------------------------------------------------
extern "C" void kernel_launch(void* const* d_in, const int* in_sizes, int n_in,
                              void* d_out, int out_size)
{
    const float* x   = (const float*)d_in[0];
    const float* cw  = (const float*)d_in[1];
    const float* cb  = (const float*)d_in[2];
    const float* c2w = (const float*)d_in[3];
    const float* c2b = (const float*)d_in[4];
    const float* sk  = (const float*)d_in[5];
    float* out = (float*)d_out;

    static bool attr_set = false;
    if (!attr_set) {
        cudaFuncSetAttribute(conv_mma_kernel,
                             cudaFuncAttributeMaxDynamicSharedMemorySize, DYN_SMEM);
        attr_set = true;
    }

    wt_transform<<<144, 256>>>(cw);
    conv_mma_kernel<<<256, 256, DYN_SMEM>>>(x, cb);
    bn_stats<<<64, 256>>>();
    attend_kernel<<<NPIX / 128, 128>>>(x, sk, c2w, c2b, out);
    agg_kernel<<<NPIX / 256, 256>>>(x, out);
}

// round 8
// speedup vs baseline: 1.6071x; 1.0742x over previous
#include <cuda_runtime.h>
#include <cstdint>

#define BATCH 8
#define CIN   64
#define COUT  64
#define Hdim  64
#define Wdim  64
#define CTOT  69
#define HW    (Hdim*Wdim)
#define NPIX  (BATCH*HW)

// Scratch (static device globals — no allocation)
__device__ float g_conv[BATCH*COUT*HW];   // raw conv output (pre-BN)
__device__ float g_sq[NPIX];              // 1x1-conv "shape query"
__device__ float g_mu[COUT];
__device__ float g_rs[COUT];
__device__ __align__(16) float g_wt[9*4096];  // weights in B-fragment order

__device__ __forceinline__ int clampi(int v, int lo, int hi) {
    return v < lo ? lo : (v > hi ? hi : v);
}
__device__ __forceinline__ float f2tf32f(float f) {
    uint32_t r; asm("cvt.rna.tf32.f32 %0, %1;" : "=r"(r) : "f"(f));
    return __uint_as_float(r);
}

// m16n8k8 tf32 mma: D += A*B (D==C, fp32 accum). a: 4 regs, b: 2 regs.
__device__ __forceinline__ void mma8(float* d, const uint32_t* a, uint32_t b0, uint32_t b1) {
    asm volatile(
        "mma.sync.aligned.m16n8k8.row.col.f32.tf32.tf32.f32 "
        "{%0,%1,%2,%3}, {%4,%5,%6,%7}, {%8,%9}, {%0,%1,%2,%3};\n"
        : "+f"(d[0]), "+f"(d[1]), "+f"(d[2]), "+f"(d[3])
        : "r"(a[0]), "r"(a[1]), "r"(a[2]), "r"(a[3]), "r"(b0), "r"(b1));
}

// ---------------------------------------------------------------------------
// Kernel 0: transform conv weights into B-fragment order (tf32-rounded).
// ---------------------------------------------------------------------------
__global__ __launch_bounds__(256) void wt_transform(const float* __restrict__ cw)
{
    int idx = blockIdx.x * 256 + threadIdx.x;
    if (idx >= 9 * 4096) return;
    int r    = idx & 1;
    int lane = (idx >> 1) & 31;
    int nt   = (idx >> 6) & 7;
    int kk   = (idx >> 9) & 7;
    int kidx = idx >> 12;
    int gid = lane >> 2, tig = lane & 3;
    int co = nt * 8 + gid;
    int ci = kk * 8 + tig + 4 * r;
    g_wt[idx] = f2tf32f(cw[(co * CIN + ci) * 9 + kidx]);
}

// ---------------------------------------------------------------------------
// Kernel 1: 3x3 conv (replication pad) via mma.sync tf32 implicit GEMM.
// (unchanged from the 59.6us version)
// ---------------------------------------------------------------------------
#define SLAB_STRIDE 264
#define SLAB_FLOATS (64*SLAB_STRIDE)          // 16896
#define BBUF_FLOATS 4096
#define DYN_SMEM ((SLAB_FLOATS + BBUF_FLOATS) * 4)   // 83968 B

__global__ __launch_bounds__(256, 2) void conv_mma_kernel(
    const float* __restrict__ x, const float* __restrict__ cb)
{
    extern __shared__ float smem[];
    float* slab = smem;                 // [64 ci][256 rc] stride 264
    float* bbuf = smem + SLAB_FLOATS;   // B fragments for current (ky,kx)

    const int tid  = threadIdx.x;
    const int lane = tid & 31;
    const int w    = tid >> 5;
    const int gid  = lane >> 2;
    const int tig  = lane & 3;
    const int wm   = (w & 3) * 32;      // pixel offset
    const int wn   = (w >> 2) * 32;     // cout offset
    const int blk  = blockIdx.x;
    const int b    = blk >> 5;
    const int h0   = (blk & 31) * 2;

    const float* xb = x + (size_t)b * CTOT * HW;
    #pragma unroll
    for (int i = 0; i < 64; i++) {
        int idx = i * 256 + tid;
        int ci  = idx >> 8;
        int rc  = idx & 255;
        int rr  = rc >> 6;
        int col = rc & 63;
        int row = clampi(h0 - 1 + rr, 0, Hdim - 1);
        slab[ci * SLAB_STRIDE + rc] = f2tf32f(__ldg(xb + (ci * Hdim + row) * Wdim + col));
    }

    const float4* wt4 = (const float4*)g_wt;
    float4 pf[4];
    #pragma unroll
    for (int j = 0; j < 4; j++) pf[j] = __ldg(wt4 + j * 256 + tid);

    float acc[2][4][4];
    #pragma unroll
    for (int tm = 0; tm < 2; tm++)
        #pragma unroll
        for (int nt = 0; nt < 4; nt++)
            #pragma unroll
            for (int c = 0; c < 4; c++) acc[tm][nt][c] = 0.f;

    __syncthreads();   // slab ready

    int dy[2], col_lo[2], col_hi[2];
    #pragma unroll
    for (int tm = 0; tm < 2; tm++) {
        int pix = wm + tm * 16 + gid;
        dy[tm] = pix >> 6;
        col_lo[tm] = pix & 63;
        col_hi[tm] = col_lo[tm] + 8;
    }

    float4* bb4 = (float4*)bbuf;

    for (int kidx = 0; kidx < 9; kidx++) {
        const int ky = kidx / 3, kx = kidx % 3;
        if (kidx > 0) __syncthreads();
        #pragma unroll
        for (int j = 0; j < 4; j++) bb4[j * 256 + tid] = pf[j];
        __syncthreads();
        if (kidx < 8) {
            #pragma unroll
            for (int j = 0; j < 4; j++)
                pf[j] = __ldg(wt4 + (kidx + 1) * 1024 + j * 256 + tid);
        }

        int off_lo[2], off_hi[2];
        #pragma unroll
        for (int tm = 0; tm < 2; tm++) {
            int rowoff = (dy[tm] + ky) * 64;
            off_lo[tm] = rowoff + clampi(col_lo[tm] + kx - 1, 0, 63);
            off_hi[tm] = rowoff + clampi(col_hi[tm] + kx - 1, 0, 63);
        }

        #pragma unroll
        for (int kk = 0; kk < 8; kk++) {
            const int cib  = (kk * 8 + tig) * SLAB_STRIDE;
            const int cib4 = cib + 4 * SLAB_STRIDE;
            uint32_t a[2][4];
            #pragma unroll
            for (int tm = 0; tm < 2; tm++) {
                a[tm][0] = __float_as_uint(slab[cib  + off_lo[tm]]);
                a[tm][1] = __float_as_uint(slab[cib  + off_hi[tm]]);
                a[tm][2] = __float_as_uint(slab[cib4 + off_lo[tm]]);
                a[tm][3] = __float_as_uint(slab[cib4 + off_hi[tm]]);
            }
            #pragma unroll
            for (int nt = 0; nt < 4; nt++) {
                int ntg = (wn >> 3) + nt;
                float2 bf = *(const float2*)&bbuf[((kk * 8 + ntg) * 32 + lane) * 2];
                uint32_t b0 = __float_as_uint(bf.x);
                uint32_t b1 = __float_as_uint(bf.y);
                mma8(acc[0][nt], a[0], b0, b1);
                mma8(acc[1][nt], a[1], b0, b1);
            }
        }
    }

    #pragma unroll
    for (int tm = 0; tm < 2; tm++) {
        float* grow = g_conv + ((size_t)b * COUT * Hdim + (h0 + dy[tm])) * Wdim;
        #pragma unroll
        for (int nt = 0; nt < 4; nt++) {
            int co0 = wn + nt * 8 + 2 * tig;
            float b0 = __ldg(cb + co0), b1 = __ldg(cb + co0 + 1);
            grow[(size_t)co0       * HW + col_lo[tm]] = acc[tm][nt][0] + b0;
            grow[(size_t)(co0 + 1) * HW + col_lo[tm]] = acc[tm][nt][1] + b1;
            grow[(size_t)co0       * HW + col_hi[tm]] = acc[tm][nt][2] + b0;
            grow[(size_t)(co0 + 1) * HW + col_hi[tm]] = acc[tm][nt][3] + b1;
        }
    }
}

// ---------------------------------------------------------------------------
// Kernel 2: BN stats, one block per channel, deterministic fixed-order tree
// ---------------------------------------------------------------------------
__global__ __launch_bounds__(256) void bn_stats()
{
    __shared__ float ss[256], ss2[256];
    const int co = blockIdx.x;
    const int t  = threadIdx.x;
    float s = 0.f, s2 = 0.f;
    #pragma unroll
    for (int b = 0; b < BATCH; b++) {
        const float4* p = (const float4*)(g_conv + ((size_t)(b * COUT + co)) * HW);
        #pragma unroll
        for (int j = 0; j < 4; j++) {
            float4 v = __ldg(p + t + j * 256);
            s  += v.x + v.y + v.z + v.w;
            s2 += v.x * v.x + v.y * v.y + v.z * v.z + v.w * v.w;
        }
    }
    ss[t] = s; ss2[t] = s2;
    __syncthreads();
    for (int o = 128; o > 0; o >>= 1) {
        if (t < o) { ss[t] += ss[t + o]; ss2[t] += ss2[t + o]; }
        __syncthreads();
    }
    if (t == 0) {
        float n   = (float)(BATCH * HW);
        float mu  = ss[0] / n;
        float var = ss2[0] / n - mu * mu;
        g_mu[co] = mu;
        g_rs[co] = rsqrtf(var + 1e-5f);
    }
}

// ---------------------------------------------------------------------------
// Kernel 3: codebook logits + channel softmax + BN-normalize + relu-attend
//           + 1x1 conv to shape query. One thread per pixel.
// logits = 2<sw,k> - |k|^2 (|sw|^2 cancels in softmax).
// Codebook TRANSPOSED in smem (s_kT[t][co]) -> float4 broadcast loads,
// 4 codes per iteration with 4 independent FMA chains (ILP).
// ---------------------------------------------------------------------------
__global__ __launch_bounds__(128) void attend_kernel(
    const float* __restrict__ x, const float* __restrict__ sk,
    const float* __restrict__ c2w, const float* __restrict__ c2b,
    float* __restrict__ out)
{
    __shared__ __align__(16) float s_kT[45 * 64];   // [t][co]
    __shared__ float s_k2[64];
    __shared__ float s_w2[64];
    __shared__ float s_mu[64];
    __shared__ float s_rs[64];
    __shared__ float s_e[128][65];

    const int tid = threadIdx.x;
    // transpose codebook: s_kT[t*64+co] = sk[co*45+t]
    for (int i = tid; i < 64 * 45; i += 128) {
        int co = i / 45, t = i - co * 45;
        s_kT[t * 64 + co] = sk[i];
    }
    if (tid < 64) { s_w2[tid] = c2w[tid]; s_mu[tid] = g_mu[tid]; s_rs[tid] = g_rs[tid]; }
    __syncthreads();
    if (tid < 64) {
        float a = 0.f;
        #pragma unroll
        for (int t2 = 0; t2 < 45; t2++) {
            float kv = s_kT[t2 * 64 + tid];
            a = fmaf(kv, kv, a);
        }
        s_k2[tid] = a;
    }
    __syncthreads();

    const int p  = blockIdx.x * 128 + tid;
    const int b  = p >> 12;
    const int hw = p & 4095;
    const int h  = hw >> 6;
    const int w  = hw & 63;

    float sw[45];
    #pragma unroll
    for (int c = 0; c < 5; c++) {
        #pragma unroll
        for (int i = 0; i < 3; i++)
            #pragma unroll
            for (int j = 0; j < 3; j++) {
                int gy = clampi(h + i - 1, 0, Hdim - 1);
                int gx = clampi(w + j - 1, 0, Wdim - 1);
                sw[c * 9 + i * 3 + j] = x[((b * CTOT + 64 + c) * Hdim + gy) * Wdim + gx];
            }
    }
    #pragma unroll
    for (int c = 0; c < 2; c++) {
        float ctr = sw[c * 9 + 4];
        #pragma unroll
        for (int k = 0; k < 9; k++) sw[c * 9 + k] -= ctr;
    }

    // ---- logits, 4 codes per iteration (4 independent chains) ----
    float lmax = -3.4e38f;
    #pragma unroll 4
    for (int co = 0; co < 64; co += 4) {
        float d0 = 0.f, d1 = 0.f, d2 = 0.f, d3 = 0.f;
        #pragma unroll
        for (int t2 = 0; t2 < 45; t2++) {
            float s = sw[t2];
            float4 k4 = *(const float4*)&s_kT[t2 * 64 + co];
            d0 = fmaf(s, k4.x, d0);
            d1 = fmaf(s, k4.y, d1);
            d2 = fmaf(s, k4.z, d2);
            d3 = fmaf(s, k4.w, d3);
        }
        float4 k2 = *(const float4*)&s_k2[co];
        float l0 = 2.f * d0 - k2.x;
        float l1 = 2.f * d1 - k2.y;
        float l2 = 2.f * d2 - k2.z;
        float l3 = 2.f * d3 - k2.w;
        s_e[tid][co]     = l0;
        s_e[tid][co + 1] = l1;
        s_e[tid][co + 2] = l2;
        s_e[tid][co + 3] = l3;
        lmax = fmaxf(lmax, fmaxf(fmaxf(l0, l1), fmaxf(l2, l3)));
    }

    // ---- softmax denominator ----
    float se = 0.f;
    #pragma unroll 4
    for (int co = 0; co < 64; co++) {
        float e = __expf(s_e[tid][co] - lmax);
        s_e[tid][co] = e;
        se += e;
    }
    float inv = 1.f / se;

    // ---- attend + 1x1 conv ----
    float sq = c2b[0];
    #pragma unroll 4
    for (int co = 0; co < 64; co++) {
        float wv  = s_e[tid][co] * inv;
        float cv  = (g_conv[((b * COUT + co) * Hdim + h) * Wdim + w] - s_mu[co]) * s_rs[co];
        float att = fmaxf(cv * wv, 0.f);
        out[((b * CTOT + co) * Hdim + h) * Wdim + w] = att;
        sq = fmaf(s_w2[co], att, sq);
    }
    g_sq[p] = sq;
}

// ---------------------------------------------------------------------------
// Kernel 4: window softmax of shape query (zero-padded) + weighted stats
// ---------------------------------------------------------------------------
__global__ __launch_bounds__(256) void agg_kernel(
    const float* __restrict__ x, float* __restrict__ out)
{
    const int p = blockIdx.x * 256 + threadIdx.x;
    if (p >= NPIX) return;
    const int b  = p >> 12;
    const int hw = p & 4095;
    const int h  = hw >> 6;
    const int w  = hw & 63;

    float qv[9];
    float qmax = -3.4e38f;
    #pragma unroll
    for (int i = 0; i < 3; i++)
        #pragma unroll
        for (int j = 0; j < 3; j++) {
            int yy = h + i - 1, xx = w + j - 1;
            float v = 0.f;
            if (yy >= 0 && yy < Hdim && xx >= 0 && xx < Wdim)
                v = g_sq[(b << 12) + (yy << 6) + xx];
            qv[i * 3 + j] = v;
            qmax = fmaxf(qmax, v);
        }
    float qs = 0.f;
    #pragma unroll
    for (int k = 0; k < 9; k++) { qv[k] = __expf(qv[k] - qmax); qs += qv[k]; }
    float qinv = 1.f / qs;
    #pragma unroll
    for (int k = 0; k < 9; k++) qv[k] *= qinv;

    float win[5][9];
    #pragma unroll
    for (int c = 0; c < 5; c++) {
        #pragma unroll
        for (int i = 0; i < 3; i++)
            #pragma unroll
            for (int j = 0; j < 3; j++) {
                int gy = clampi(h + i - 1, 0, Hdim - 1);
                int gx = clampi(w + j - 1, 0, Wdim - 1);
                win[c][i * 3 + j] = x[((b * CTOT + 64 + c) * Hdim + gy) * Wdim + gx];
            }
    }

    float mean0 = 0.f, mean1 = 0.f, v1_0 = 0.f, v1_1 = 0.f, c1 = 0.f;
    #pragma unroll
    for (int k = 0; k < 9; k++) {
        mean0 = fmaf(win[0][k], qv[k], mean0);
        mean1 = fmaf(win[1][k], qv[k], mean1);
        v1_0  = fmaf(win[2][k], qv[k], v1_0);
        v1_1  = fmaf(win[3][k], qv[k], v1_1);
        c1    = fmaf(win[4][k], qv[k], c1);
    }
    float v2_0 = 0.f, v2_1 = 0.f, c2 = 0.f;
    #pragma unroll
    for (int k = 0; k < 9; k++) {
        float d0 = win[0][k] - mean0;
        float d1 = win[1][k] - mean1;
        v2_0 = fmaf(d0 * d0, qv[k], v2_0);
        v2_1 = fmaf(d1 * d1, qv[k], v2_1);
        c2   = fmaf(d0 * d1, qv[k], c2);
    }

    out[((b * CTOT + 64) * Hdim + h) * Wdim + w] = mean0;
    out[((b * CTOT + 65) * Hdim + h) * Wdim + w] = mean1;
    out[((b * CTOT + 66) * Hdim + h) * Wdim + w] = v1_0 + v2_0;
    out[((b * CTOT + 67) * Hdim + h) * Wdim + w] = v1_1 + v2_1;
    out[((b * CTOT + 68) * Hdim + h) * Wdim + w] = c1 + c2;
}

// ---------------------------------------------------------------------------
extern "C" void kernel_launch(void* const* d_in, const int* in_sizes, int n_in,
                              void* d_out, int out_size)
{
    const float* x   = (const float*)d_in[0];
    const float* cw  = (const float*)d_in[1];
    const float* cb  = (const float*)d_in[2];
    const float* c2w = (const float*)d_in[3];
    const float* c2b = (const float*)d_in[4];
    const float* sk  = (const float*)d_in[5];
    float* out = (float*)d_out;

    static bool attr_set = false;
    if (!attr_set) {
        cudaFuncSetAttribute(conv_mma_kernel,
                             cudaFuncAttributeMaxDynamicSharedMemorySize, DYN_SMEM);
        attr_set = true;
    }

    wt_transform<<<144, 256>>>(cw);
    conv_mma_kernel<<<256, 256, DYN_SMEM>>>(x, cb);
    bn_stats<<<64, 256>>>();
    attend_kernel<<<NPIX / 128, 128>>>(x, sk, c2w, c2b, out);
    agg_kernel<<<NPIX / 256, 256>>>(x, out);
}